// round 5
// baseline (speedup 1.0000x reference)
#include <cuda_runtime.h>
#include <cuda_bf16.h>
#include <cstdint>

#define BNtok 65536
#define Dh    512
#define Kcb   1024
#define DSc   256

#define MARGIN 2.5e-3f
#define CAP    16
#define SWQ    (1.0f / 130048.0f)   // W quant scale: (1/1024)/127
#define WPITCH 272                  // int8 code row pitch (256 + 16 pad)

// ---------------- device scratch -------------------------------------------
__device__ __align__(16) uint8_t g_wq8[(size_t)2 * Kcb * WPITCH];
__device__ float  g_wsq[2 * Kcb];
__device__ int    g_ids[2 * BNtok];
__device__ double g_loss;

// ---------------- helpers --------------------------------------------------
static __device__ __forceinline__ uint32_t smem_u32(const void* p) {
    uint32_t a;
    asm("{ .reg .u64 t; cvta.to.shared.u64 t, %1; cvt.u32.u64 %0, t; }" : "=r"(a) : "l"(p));
    return a;
}

#define IMMA16832(d, a0, a1, a2, a3, b0, b1) \
    asm volatile("mma.sync.aligned.m16n8k32.row.col.s32.s8.s8.s32 " \
        "{%0,%1,%2,%3}, {%4,%5,%6,%7}, {%8,%9}, {%0,%1,%2,%3};" \
        : "+r"((d)[0]), "+r"((d)[1]), "+r"((d)[2]), "+r"((d)[3]) \
        : "r"(a0), "r"(a1), "r"(a2), "r"(a3), "r"(b0), "r"(b1))

#define CP_ASYNC16(saddr, gptr) \
    asm volatile("cp.async.cg.shared.global [%0], [%1], 16;" :: "r"(saddr), "l"(gptr))
#define CP_COMMIT() asm volatile("cp.async.commit_group;" ::: "memory")

static __device__ __forceinline__ uint32_t ldsm_b32(uint32_t addr) {
    uint32_t v;
    asm volatile("ld.shared.b32 %0, [%1];" : "=r"(v) : "r"(addr));
    return v;
}

static __device__ __forceinline__ uint32_t pack4s8(int a, int b, int c, int d) {
    return (uint32_t)(a & 0xFF) | ((uint32_t)(b & 0xFF) << 8) |
           ((uint32_t)(c & 0xFF) << 16) | ((uint32_t)(d & 0xFF) << 24);
}

// ---------------- smem layout (bytes) --------------------------------------
#define BOFF   0        // B stages: 2 x (128 codes x 272) = 69632 ; stage0 aliases xq staging
#define WSQO   69632    // 1024 f32
#define CANDO  73728    // 128 x CAP u16
#define SCNTO  77824    // 128 int
#define SXO    78336    // 128 f32 (per-token 2*sx*swq)
#define SMEM_SZ 78848

// ---------------------------------------------------------------------------
// prep: W -> int8 (pitch 272) + fp32 w_sq + zero loss. 256 blk x 256 thr,
// one warp per code (2048 codes).
// ---------------------------------------------------------------------------
__global__ void prep_kernel(const float* __restrict__ W) {
    int gid  = blockIdx.x * 256 + threadIdx.x;
    if (gid == 0) g_loss = 0.0;
    int code = gid >> 5;
    int lane = gid & 31;
    const float4* W4 = (const float4*)W;

    float4 v0 = W4[(size_t)code * 64 + lane * 2];
    float4 v1 = W4[(size_t)code * 64 + lane * 2 + 1];

    float s = v0.x * v0.x + v0.y * v0.y + v0.z * v0.z + v0.w * v0.w
            + v1.x * v1.x + v1.y * v1.y + v1.z * v1.z + v1.w * v1.w;
    #pragma unroll
    for (int o = 16; o > 0; o >>= 1) s += __shfl_xor_sync(0xffffffffu, s, o);
    if (lane == 0) g_wsq[code] = s;

    const float inv = 130048.0f;  // 1/SWQ
    int q0 = __float2int_rn(v0.x * inv), q1 = __float2int_rn(v0.y * inv);
    int q2 = __float2int_rn(v0.z * inv), q3 = __float2int_rn(v0.w * inv);
    int q4 = __float2int_rn(v1.x * inv), q5 = __float2int_rn(v1.y * inv);
    int q6 = __float2int_rn(v1.z * inv), q7 = __float2int_rn(v1.w * inv);
    q0 = max(-127, min(127, q0)); q1 = max(-127, min(127, q1));
    q2 = max(-127, min(127, q2)); q3 = max(-127, min(127, q3));
    q4 = max(-127, min(127, q4)); q5 = max(-127, min(127, q5));
    q6 = max(-127, min(127, q6)); q7 = max(-127, min(127, q7));
    uint2 pk = make_uint2(pack4s8(q0, q1, q2, q3), pack4s8(q4, q5, q6, q7));
    *(uint2*)(g_wq8 + (size_t)code * WPITCH + lane * 8) = pk;
}

// ---------------------------------------------------------------------------
// fused: int8 IMMA scoring + candidate capture + exact fp32 rescore + z + loss
// grid 1024 (512 token-tiles x 2 slices), 256 thr (8 warps), 2 blocks/SM.
// warp w owns tokens [w*16, w*16+16)
// ---------------------------------------------------------------------------
__global__ void __launch_bounds__(256, 2)
vq_kernel(const float* __restrict__ h, const float* __restrict__ W,
          float* __restrict__ out) {
    extern __shared__ __align__(1024) uint8_t smem[];
    const uint32_t sb = smem_u32(smem);

    const int tid = threadIdx.x;
    const int wid = tid >> 5;
    const int lid = tid & 31;
    const int r4  = lid >> 2;   // fragment row / code sub-index
    const int q4  = lid & 3;    // fragment quad index
    const int blk = blockIdx.x;
    const int s   = blk >> 9;
    const int m0  = (blk & 511) * 128;

    float*    swsq  = (float*)(smem + WSQO);
    uint16_t* candp = (uint16_t*)(smem + CANDO);
    int*      scnt  = (int*)(smem + SCNTO);
    float*    sxs   = (float*)(smem + SXO);

    if (tid < 128) scnt[tid] = 0;
    #pragma unroll
    for (int i = 0; i < 4; i++) swsq[i * 256 + tid] = g_wsq[s * Kcb + i * 256 + tid];

    // ---- x: per-token amax -> int8 quantize into smem staging (stage0 area)
    const float4* h4 = (const float4*)h;
    for (int j = 0; j < 16; j++) {
        const int trow = wid * 16 + j;
        const int m    = m0 + trow;
        float4 v0 = h4[(size_t)m * (Dh / 4) + s * (DSc / 4) + lid * 2];
        float4 v1 = h4[(size_t)m * (Dh / 4) + s * (DSc / 4) + lid * 2 + 1];
        float mx = fmaxf(fmaxf(fmaxf(fabsf(v0.x), fabsf(v0.y)), fmaxf(fabsf(v0.z), fabsf(v0.w))),
                         fmaxf(fmaxf(fabsf(v1.x), fabsf(v1.y)), fmaxf(fabsf(v1.z), fabsf(v1.w))));
        #pragma unroll
        for (int o = 16; o > 0; o >>= 1)
            mx = fmaxf(mx, __shfl_xor_sync(0xffffffffu, mx, o));
        float inv = (mx > 0.f) ? (127.0f / mx) : 0.f;
        if (lid == 0) sxs[trow] = 2.0f * (mx / 127.0f) * SWQ;
        int q0 = __float2int_rn(v0.x * inv), q1 = __float2int_rn(v0.y * inv);
        int q2 = __float2int_rn(v0.z * inv), q3 = __float2int_rn(v0.w * inv);
        int q4i = __float2int_rn(v1.x * inv), q5 = __float2int_rn(v1.y * inv);
        int q6 = __float2int_rn(v1.z * inv), q7 = __float2int_rn(v1.w * inv);
        uint2 pk = make_uint2(pack4s8(q0, q1, q2, q3), pack4s8(q4i, q5, q6, q7));
        *(uint2*)(smem + BOFF + (size_t)trow * WPITCH + lid * 8) = pk;
    }
    __syncthreads();

    // ---- build resident A fragments (8 kchunks x 4 regs) from staging ----
    uint32_t a[8][4];
    {
        const uint32_t aA = sb + BOFF + (uint32_t)(wid * 16 + r4) * WPITCH + q4 * 4;
        const uint32_t aB = aA + 8 * WPITCH;
        #pragma unroll
        for (int c = 0; c < 8; c++) {
            a[c][0] = ldsm_b32(aA + c * 32);
            a[c][1] = ldsm_b32(aB + c * 32);
            a[c][2] = ldsm_b32(aA + c * 32 + 16);
            a[c][3] = ldsm_b32(aB + c * 32 + 16);
        }
    }
    float c2A = 0.f, c2B = 0.f;  // set after sync (sxs ready now)
    c2A = sxs[wid * 16 + r4];
    c2B = sxs[wid * 16 + r4 + 8];
    __syncthreads();   // staging fully consumed; B prefetch may overwrite

    // ---- prefetch B tiles 0,1 (128 codes x 272B = 34816B each) ----
    const uint8_t* wsrc = g_wq8 + (size_t)s * Kcb * WPITCH;
    #pragma unroll
    for (int p = 0; p < 2; p++) {
        const uint8_t* src = wsrc + (size_t)p * 34816;
        uint32_t dst = sb + BOFF + p * 34816;
        #pragma unroll
        for (int i = 0; i < 9; i++) {
            int idx = i * 256 + tid;
            if (idx < 2176) CP_ASYNC16(dst + idx * 16, src + (size_t)idx * 16);
        }
        CP_COMMIT();
    }

    float vminA = 1e30f, vminB = 1e30f;
    const int tokA = wid * 16 + r4;
    const int tokB = tokA + 8;
    const uint32_t laneB = (uint32_t)(r4 * WPITCH + q4 * 4);

    for (int tile = 0; tile < 8; tile++) {
        if (tile < 7) asm volatile("cp.async.wait_group 1;" ::: "memory");
        else          asm volatile("cp.async.wait_group 0;" ::: "memory");
        __syncthreads();

        const uint32_t bbase = sb + BOFF + (tile & 1) * 34816 + laneB;

        #pragma unroll
        for (int half = 0; half < 2; half++) {
            int32_t acc[8][4];
            #pragma unroll
            for (int nb = 0; nb < 8; nb++)
                #pragma unroll
                for (int e = 0; e < 4; e++) acc[nb][e] = 0;

            #pragma unroll
            for (int c = 0; c < 8; c++) {
                #pragma unroll
                for (int nb = 0; nb < 8; nb++) {
                    uint32_t addr = bbase + (uint32_t)((half * 8 + nb) * 8) * WPITCH + c * 32;
                    uint32_t b0 = ldsm_b32(addr);
                    uint32_t b1 = ldsm_b32(addr + 16);
                    IMMA16832(acc[nb], a[c][0], a[c][1], a[c][2], a[c][3], b0, b1);
                }
            }

            // epilogue on 8 col-blocks
            float scf[8][4];
            float mnA = 1e30f, mnB = 1e30f;
            const int kb = tile * 128 + half * 64 + 2 * q4;
            #pragma unroll
            for (int nb = 0; nb < 8; nb++) {
                float2 wv = *(const float2*)(swsq + kb + nb * 8);
                float f0 = (float)acc[nb][0], f1 = (float)acc[nb][1];
                float f2 = (float)acc[nb][2], f3 = (float)acc[nb][3];
                scf[nb][0] = fmaf(-c2A, f0, wv.x);
                scf[nb][1] = fmaf(-c2A, f1, wv.y);
                scf[nb][2] = fmaf(-c2B, f2, wv.x);
                scf[nb][3] = fmaf(-c2B, f3, wv.y);
                mnA = fminf(mnA, fminf(scf[nb][0], scf[nb][1]));
                mnB = fminf(mnB, fminf(scf[nb][2], scf[nb][3]));
            }
            mnA = fminf(mnA, __shfl_xor_sync(0xffffffffu, mnA, 1));
            mnA = fminf(mnA, __shfl_xor_sync(0xffffffffu, mnA, 2));
            mnB = fminf(mnB, __shfl_xor_sync(0xffffffffu, mnB, 1));
            mnB = fminf(mnB, __shfl_xor_sync(0xffffffffu, mnB, 2));
            vminA = fminf(vminA, mnA);
            vminB = fminf(vminB, mnB);
            const float thA = vminA + MARGIN;
            const float thB = vminB + MARGIN;
            #pragma unroll
            for (int nb = 0; nb < 8; nb++) {
                int k0 = kb + nb * 8;
                if (scf[nb][0] < thA) { int sl = atomicAdd(&scnt[tokA], 1); if (sl < CAP) candp[tokA * CAP + sl] = (uint16_t)k0; }
                if (scf[nb][1] < thA) { int sl = atomicAdd(&scnt[tokA], 1); if (sl < CAP) candp[tokA * CAP + sl] = (uint16_t)(k0 + 1); }
                if (scf[nb][2] < thB) { int sl = atomicAdd(&scnt[tokB], 1); if (sl < CAP) candp[tokB * CAP + sl] = (uint16_t)k0; }
                if (scf[nb][3] < thB) { int sl = atomicAdd(&scnt[tokB], 1); if (sl < CAP) candp[tokB * CAP + sl] = (uint16_t)(k0 + 1); }
            }
        }

        __syncthreads();
        if (tile + 2 < 8) {
            const uint8_t* src = wsrc + (size_t)(tile + 2) * 34816;
            uint32_t dst = sb + BOFF + (tile & 1) * 34816;
            #pragma unroll
            for (int i = 0; i < 9; i++) {
                int idx = i * 256 + tid;
                if (idx < 2176) CP_ASYNC16(dst + idx * 16, src + (size_t)idx * 16);
            }
            CP_COMMIT();
        }
    }

    // ---- exact rescore + z write + loss (warp owns its 16 tokens) ----
    const float4* W4 = (const float4*)W;
    float4* o4 = (float4*)out;
    float lsum = 0.f;

    for (int tl = 0; tl < 16; tl++) {
        const int tok = wid * 16 + tl;
        const int m   = m0 + tok;
        const int tc  = scnt[tok];

        const float4* xr = h4 + (size_t)m * (Dh / 4) + s * (DSc / 4);
        float4 xa = xr[lid * 2];
        float4 xb = xr[lid * 2 + 1];
        float xs = xa.x * xa.x + xa.y * xa.y + xa.z * xa.z + xa.w * xa.w
                 + xb.x * xb.x + xb.y * xb.y + xb.z * xb.z + xb.w * xb.w;
        #pragma unroll
        for (int o = 16; o > 0; o >>= 1) xs += __shfl_xor_sync(0xffffffffu, xs, o);

        const int ncand = (tc > CAP) ? Kcb : tc;
        float best = 1e30f;
        int   bid  = 0x7fffffff;
        for (int j = 0; j < ncand; j++) {
            const int k = (tc > CAP) ? j : (int)candp[tok * CAP + j];
            const float4* wr = W4 + ((size_t)s * Kcb + k) * (DSc / 4);
            float4 wa = wr[lid * 2];
            float4 wb = wr[lid * 2 + 1];
            float dp = xa.x * wa.x + xa.y * wa.y + xa.z * wa.z + xa.w * wa.w
                     + xb.x * wb.x + xb.y * wb.y + xb.z * wb.z + xb.w * wb.w;
            #pragma unroll
            for (int o = 16; o > 0; o >>= 1) dp += __shfl_xor_sync(0xffffffffu, dp, o);
            float dist = (xs + swsq[k]) - 2.0f * dp;
            if (dist < best || (dist == best && k < bid)) { best = dist; bid = k; }
        }

        if (lid == 0) {
            g_ids[s * BNtok + m] = bid;
            lsum += best;
        }
        const float4* wrw = W4 + ((size_t)s * Kcb + bid) * (DSc / 4);
        float4* orow = o4 + (size_t)m * (Dh / 4) + s * (DSc / 4);
        orow[lid * 2]     = wrw[lid * 2];
        orow[lid * 2 + 1] = wrw[lid * 2 + 1];
    }
    if (lid == 0) atomicAdd(&g_loss, (double)lsum);
}

// ---------------------------------------------------------------------------
__global__ void pack_kernel(float* __restrict__ out) {
    int m = blockIdx.x * 256 + threadIdx.x;
    out[(size_t)BNtok * Dh + m] = (float)(g_ids[m] + Kcb * g_ids[BNtok + m]);
}

__global__ void finalize_kernel(float* __restrict__ out) {
    out[(size_t)BNtok * Dh + BNtok] = (float)(1.25 * g_loss / 16777216.0);
}

// ---------------------------------------------------------------------------
extern "C" void kernel_launch(void* const* d_in, const int* in_sizes, int n_in,
                              void* d_out, int out_size) {
    const float* h = (const float*)d_in[0];
    const float* W = (const float*)d_in[1];
    if (n_in >= 2 && in_sizes[0] == 2 * Kcb * DSc) {  // defensive swap
        const float* tp = h; h = W; W = tp;
    }
    float* out = (float*)d_out;

    cudaFuncSetAttribute(vq_kernel, cudaFuncAttributeMaxDynamicSharedMemorySize, SMEM_SZ);

    prep_kernel<<<256, 256>>>(W);
    vq_kernel<<<1024, 256, SMEM_SZ>>>(h, W, out);

    if (out_size >= BNtok * Dh + BNtok)
        pack_kernel<<<BNtok / 256, 256>>>(out);
    if (out_size >= BNtok * Dh + BNtok + 1)
        finalize_kernel<<<1, 1>>>(out);
}